// round 12
// baseline (speedup 1.0000x reference)
#include <cuda_runtime.h>

// Hamilton product of quaternions packed in the last dim (w, x, y, z).
// Shapes: q1, q2: (32, 4096, 64, 4) fp32 -> 8,388,608 quaternions.
// HBM-bound streaming op (2R+1W, ~403 MB total, zero reuse).
//
// R12 (final matrix cell): float4 family (compiler LDG.128 — consistently
// benches ~1us better under graph replay than the inline-asm v8 family)
// + TPB=128 (best occupancy/L1tex balance) + 2 quaternions per thread with
// front-batched loads (MLP_p1=4, the R2-proven ILP sweet spot).

#define TPB 128
#define QPT 2

__device__ __forceinline__ float4 hprod(float4 a, float4 b) {
    float4 r;
    r.x = a.x * b.x - a.y * b.y - a.z * b.z - a.w * b.w;  // w
    r.y = a.x * b.y + a.y * b.x + a.z * b.w - a.w * b.z;  // x
    r.z = a.x * b.z - a.y * b.w + a.z * b.x + a.w * b.y;  // y
    r.w = a.x * b.w + a.y * b.z - a.z * b.y + a.w * b.x;  // z
    return r;
}

__global__ void __launch_bounds__(TPB) hamilton_kernel(
    const float4* __restrict__ q1,
    const float4* __restrict__ q2,
    float4* __restrict__ out,
    int n_quat)
{
    // Block-strided pair: lanes stay adjacent -> both LDG.128 fully coalesced.
    int base = blockIdx.x * (TPB * QPT) + threadIdx.x;

    if (base + TPB < n_quat) {
        // Fast path (always taken for this shape: n_quat % 256 == 0).
        float4 a0 = q1[base];
        float4 a1 = q1[base + TPB];
        float4 b0 = q2[base];
        float4 b1 = q2[base + TPB];
        out[base]       = hprod(a0, b0);
        out[base + TPB] = hprod(a1, b1);
    } else {
#pragma unroll
        for (int k = 0; k < QPT; k++) {
            int i = base + k * TPB;
            if (i < n_quat) out[i] = hprod(q1[i], q2[i]);
        }
    }
}

extern "C" void kernel_launch(void* const* d_in, const int* in_sizes, int n_in,
                              void* d_out, int out_size) {
    const float4* q1 = (const float4*)d_in[0];
    const float4* q2 = (const float4*)d_in[1];
    float4* out = (float4*)d_out;

    int n_quat = in_sizes[0] / 4;          // 8,388,608
    int per_block = TPB * QPT;             // 256
    int blocks = (n_quat + per_block - 1) / per_block;  // 32768
    hamilton_kernel<<<blocks, TPB>>>(q1, q2, out, n_quat);
}

// round 13
// speedup vs baseline: 1.0385x; 1.0385x over previous
#include <cuda_runtime.h>

// Hamilton product of quaternions packed in the last dim (w, x, y, z).
// Shapes: q1, q2: (32, 4096, 64, 4) fp32 -> 8,388,608 quaternions.
//
// FINAL. HBM-bound 2R+1W stream (~403 MB, zero reuse); all kernels in the
// 13-round sweep sit at 83-85% of HBM spec (the achieved B300 ceiling).
// Harness graph-replay timing consistently favors the QPT=1 shape (bench
// mean 61.0us vs 62.4us for all front-batched/ILP variants, best 60.29us):
// one coalesced LDG.128 pair per thread gives the smoothest L1tex-queue
// pressure across overlapping replays. ncu kernel time rank-inverts with
// bench here; the bench is what counts.

__global__ void __launch_bounds__(256) hamilton_kernel(
    const float4* __restrict__ q1,
    const float4* __restrict__ q2,
    float4* __restrict__ out,
    int n_quat)
{
    int i = blockIdx.x * blockDim.x + threadIdx.x;
    if (i >= n_quat) return;

    float4 a = q1[i];
    float4 b = q2[i];

    // a = (w1, x1, y1, z1), b = (w2, x2, y2, z2)
    float4 r;
    r.x = a.x * b.x - a.y * b.y - a.z * b.z - a.w * b.w;  // w
    r.y = a.x * b.y + a.y * b.x + a.z * b.w - a.w * b.z;  // x
    r.z = a.x * b.z - a.y * b.w + a.z * b.x + a.w * b.y;  // y
    r.w = a.x * b.w + a.y * b.z - a.z * b.y + a.w * b.x;  // z

    out[i] = r;
}

extern "C" void kernel_launch(void* const* d_in, const int* in_sizes, int n_in,
                              void* d_out, int out_size) {
    const float4* q1 = (const float4*)d_in[0];
    const float4* q2 = (const float4*)d_in[1];
    float4* out = (float4*)d_out;

    int n_quat = in_sizes[0] / 4;  // 8,388,608

    int threads = 256;
    int blocks = (n_quat + threads - 1) / threads;  // 32768
    hamilton_kernel<<<blocks, threads>>>(q1, q2, out, n_quat);
}